// round 15
// baseline (speedup 1.0000x reference)
#include <cuda_runtime.h>
#include <math.h>
#include <stdint.h>

// Problem constants (fixed shapes)
#define BB   2
#define LL   2048
#define DM   1024
#define DI   2048
#define DTR  64
#define BL   (BB*LL)          // 4096
#define NSEG 16
#define SEGL (LL/NSEG)        // 128
#define CHK  8
#define NCHK (SEGL/CHK)       // 16
#define S96  ((size_t)BL * 96)

// ---------------------------------------------------------------------------
// Scratch
// ---------------------------------------------------------------------------
static const size_t XZ_OFF    = 0;
static const size_t U_OFF     = 16777216;
static const size_t DELTA_OFF = 34340864;
static const size_t Y_OFF     = 51118080;
static const size_t PP_OFF    = 67895296;   // [2][2][16][2048][16]
static const size_t EE_OFF    = 69992448;
static const size_t HS_OFF    = 72089600;
static const size_t XDP_OFF   = 74186752;   // split-K partials: 4 * BL*96
static const size_t SCRATCH_N = 75759616;

__device__ float g_scratch[SCRATCH_N];

// ---------------------------------------------------------------------------
// f32x2 helpers
// ---------------------------------------------------------------------------
__device__ __forceinline__ uint32_t smem_u32(const void* p) {
    uint32_t a;
    asm("{ .reg .u64 t; cvta.to.shared.u64 t, %1; cvt.u32.u64 %0, t; }"
        : "=r"(a) : "l"(p));
    return a;
}
__device__ __forceinline__ double pack_dup(float a) {
    double d;
    asm("mov.b64 %0, {%1, %1};" : "=d"(d) : "r"(__float_as_uint(a)));
    return d;
}
__device__ __forceinline__ double pack2(float a, float b) {   // a -> lo
    double d;
    asm("mov.b64 %0, {%1, %2};" : "=d"(d) : "r"(__float_as_uint(a)), "r"(__float_as_uint(b)));
    return d;
}
__device__ __forceinline__ void ffma2(double& c, double a, double b) {
    asm("fma.rn.f32x2 %0, %1, %2, %0;" : "+d"(c) : "d"(a), "d"(b));
}
__device__ __forceinline__ double fmul2(double a, double b) {
    double r;
    asm("mul.rn.f32x2 %0, %1, %2;" : "=d"(r) : "d"(a), "d"(b));
    return r;
}
__device__ __forceinline__ float2 unpack_f32x2(double d) {
    uint32_t lo, hi;
    asm("mov.b64 {%0, %1}, %2;" : "=r"(lo), "=r"(hi) : "d"(d));
    return make_float2(__uint_as_float(lo), __uint_as_float(hi));
}
__device__ __forceinline__ void cp16(uint32_t dst, const void* src) {
    asm volatile("cp.async.cg.shared.global [%0], [%1], 16;"
                 :: "r"(dst), "l"(src) : "memory");
}
__device__ __forceinline__ void cp_commit() {
    asm volatile("cp.async.commit_group;" ::: "memory");
}
template <int N>
__device__ __forceinline__ void cp_wait() {
    asm volatile("cp.async.wait_group %0;" :: "n"(N) : "memory");
}

// ---------------------------------------------------------------------------
// dummy (profiler alignment): launch #4 is captured -> keep G1 there (control)
// ---------------------------------------------------------------------------
__global__ void dummy_kernel(float* p) { if (threadIdx.x == 0) p[0] = 0.f; }

// ---------------------------------------------------------------------------
// f32x2 GEMM, n-pair accumulators.  (core FROZEN — 604us / fma 71%)
//   AMODE 0: plain A.   AMODE 1: A = A0[m] + A1[flipL(m)].
//   AMODE 2: A = A0[m] + A0[m + 2*aStrideZ]  (fused split-K partial sum)
// ---------------------------------------------------------------------------
#define KCH 16
#define PW  132

template <int AMODE, int EPI, int SPLIT>
__global__ void __launch_bounds__(256, 2)
gemm_np(const float* __restrict__ A0, const float* __restrict__ A1,
        size_t aStrideZ,
        const float* __restrict__ W0, const float* __restrict__ W1,
        const float* __restrict__ b0, const float* __restrict__ b1,
        float* __restrict__ C, size_t cStrideZ,
        int N, int K, int lda, int ldw, int ldc)
{
    __shared__ __align__(16) float smA[2][KCH * PW];
    __shared__ __align__(16) float smW[2][KCH * PW];

    const int tid = threadIdx.x;
    const int tx  = tid & 15;
    const int ty  = tid >> 4;
    const int z   = blockIdx.z;
    const int bm  = blockIdx.y * 128;
    const int bn  = blockIdx.x * 128;

    const int dir  = SPLIT ? (z & 1) : z;
    const int kOff = SPLIT ? (z >> 1) * K : 0;

    const float* A    = A0 + (size_t)dir * aStrideZ + kOff;
    const float* W    = (dir ? W1 : W0) + kOff;
    const float* bias = dir ? b1 : b0;
    float*       Cc   = C + (size_t)z * cStrideZ;

    const int lrow = tid >> 1;
    const int lkh  = (tid & 1) * 8;

    const float* pA = A + (size_t)(bm + lrow) * lda + lkh;
    const float* pA2 = nullptr;
    if constexpr (AMODE == 1) {
        const int gm = bm + lrow;
        const int bb2 = gm >> 11, l = gm & (LL - 1);
        pA2 = A1 + (size_t)((bb2 << 11) | (LL - 1 - l)) * lda + lkh;
    }
    if constexpr (AMODE == 2) {
        pA2 = pA + 2 * aStrideZ;
    }
    const int wrow = (bn + lrow < N) ? (bn + lrow) : (N - 1);
    const float* pW = W + (size_t)wrow * ldw + lkh;

    double acc[8][4];
#pragma unroll
    for (int i = 0; i < 8; i++)
#pragma unroll
        for (int j = 0; j < 4; j++) acc[i][j] = 0.0;

    float ra[8], rw[8];

    auto load_chunk = [&](int k0) {
        float4 v0 = *(const float4*)(pA + k0);
        float4 v1 = *(const float4*)(pA + k0 + 4);
        if constexpr (AMODE != 0) {
            float4 u0 = *(const float4*)(pA2 + k0);
            float4 u1 = *(const float4*)(pA2 + k0 + 4);
            v0.x += u0.x; v0.y += u0.y; v0.z += u0.z; v0.w += u0.w;
            v1.x += u1.x; v1.y += u1.y; v1.z += u1.z; v1.w += u1.w;
        }
        ra[0]=v0.x; ra[1]=v0.y; ra[2]=v0.z; ra[3]=v0.w;
        ra[4]=v1.x; ra[5]=v1.y; ra[6]=v1.z; ra[7]=v1.w;
        float4 w0 = *(const float4*)(pW + k0);
        float4 w1 = *(const float4*)(pW + k0 + 4);
        rw[0]=w0.x; rw[1]=w0.y; rw[2]=w0.z; rw[3]=w0.w;
        rw[4]=w1.x; rw[5]=w1.y; rw[6]=w1.z; rw[7]=w1.w;
    };
    auto store_chunk = [&](int s) {
#pragma unroll
        for (int c = 0; c < 8; c++) smA[s][(lkh + c) * PW + lrow] = ra[c];
#pragma unroll
        for (int c = 0; c < 8; c++) smW[s][(lkh + c) * PW + lrow] = rw[c];
    };

    load_chunk(0);
    store_chunk(0);
    __syncthreads();

    const int KC = K / KCH;
    for (int kc = 0; kc < KC; kc++) {
        if (kc + 1 < KC) load_chunk((kc + 1) * KCH);

        const float* As = smA[kc & 1];
        const float* Ws = smW[kc & 1];
#pragma unroll
        for (int k = 0; k < KCH; k++) {
            float4 a0 = *(const float4*)(As + k * PW + ty * 8);
            float4 a1 = *(const float4*)(As + k * PW + ty * 8 + 4);
            double2 w01 = *(const double2*)(Ws + k * PW + 4 * tx);
            double2 w23 = *(const double2*)(Ws + k * PW + 64 + 4 * tx);
            const float af[8] = {a0.x, a0.y, a0.z, a0.w, a1.x, a1.y, a1.z, a1.w};
#pragma unroll
            for (int i = 0; i < 8; i++) {
                const double ad = pack_dup(af[i]);
                ffma2(acc[i][0], ad, w01.x);
                ffma2(acc[i][1], ad, w01.y);
                ffma2(acc[i][2], ad, w23.x);
                ffma2(acc[i][3], ad, w23.y);
            }
        }

        if (kc + 1 < KC) store_chunk((kc + 1) & 1);
        __syncthreads();
    }

    const int c0 = bn + 4 * tx;
    const int c1 = bn + 64 + 4 * tx;
#pragma unroll
    for (int i = 0; i < 8; i++) {
        float2 q0 = unpack_f32x2(acc[i][0]);
        float2 q1 = unpack_f32x2(acc[i][1]);
        float2 q2 = unpack_f32x2(acc[i][2]);
        float2 q3 = unpack_f32x2(acc[i][3]);
        float o[8] = {q0.x, q0.y, q1.x, q1.y, q2.x, q2.y, q3.x, q3.y};
        if constexpr (EPI == 1) {
#pragma unroll
            for (int c = 0; c < 4; c++) {
                float v = o[c] + bias[c0 + c];
                o[c] = (v > 20.f) ? v : log1pf(__expf(v));
            }
#pragma unroll
            for (int c = 0; c < 4; c++) {
                float v = o[4 + c] + bias[c1 + c];
                o[4 + c] = (v > 20.f) ? v : log1pf(__expf(v));
            }
        }
        float* cp = Cc + (size_t)(bm + ty * 8 + i) * ldc;
        if (c0 < N) *(float4*)(cp + c0) = make_float4(o[0], o[1], o[2], o[3]);
        if (c1 < N) *(float4*)(cp + c1) = make_float4(o[4], o[5], o[6], o[7]);
    }
}

// ---------------------------------------------------------------------------
// Depthwise causal conv (d_conv=4) + SiLU, 4 timesteps/thread.
// ---------------------------------------------------------------------------
__global__ void __launch_bounds__(256)
conv_silu_kernel(const float* __restrict__ xz,
                 const float* __restrict__ cwf, const float* __restrict__ cbf,
                 const float* __restrict__ cwr, const float* __restrict__ cbr,
                 float* __restrict__ U)
{
    const int t    = blockIdx.x * 256 + threadIdx.x;
    const int dir  = blockIdx.z;
    const int d    = t & (DI - 1);
    const int bl4  = t >> 11;
    const int b    = bl4 >> 9;
    const int l0   = (bl4 & 511) * 4;

    const float* cw = dir ? cwr : cwf;
    const float bias = (dir ? cbr : cbf)[d];
    const float w0 = cw[d * 4 + 0];
    const float w1 = cw[d * 4 + 1];
    const float w2 = cw[d * 4 + 2];
    const float w3 = cw[d * 4 + 3];

    float xv[7];
#pragma unroll
    for (int j = 0; j < 7; j++) {
        const int lj = l0 - 3 + j;
        if (lj >= 0) {
            const int lsrc = dir ? (LL - 1 - lj) : lj;
            xv[j] = xz[((size_t)(b * LL + lsrc)) * (2 * DI) + d];
        } else {
            xv[j] = 0.f;
        }
    }

    const size_t ubase = (size_t)dir * ((size_t)BL * DI)
                       + ((size_t)(b * LL + l0)) * DI + d;
#pragma unroll
    for (int o = 0; o < 4; o++) {
        float s = bias;
        s = fmaf(xv[o + 0], w0, s);
        s = fmaf(xv[o + 1], w1, s);
        s = fmaf(xv[o + 2], w2, s);
        s = fmaf(xv[o + 3], w3, s);
        const float sg = 1.f / (1.f + __expf(-s));
        U[ubase + (size_t)o * DI] = s * sg;
    }
}

// ---------------------------------------------------------------------------
// Chunked selective scan + cp.async staging of delta/U/z.
// B/C read from the TWO split-K partial buffers (fused add; no addxd pass).
// PHASE 1: local scan from 0; Ssum accumulated; analytic P at segment end.
// PHASE 3: seeded scan with HS; fused y = (scan + u*D) * silu(z).
// ---------------------------------------------------------------------------
template <int PHASE>
__global__ void __launch_bounds__(128)
scan_seg(const float* __restrict__ delta, const float* __restrict__ U,
         const float* __restrict__ xdp,   const float* __restrict__ xz,
         const float* __restrict__ AlogF, const float* __restrict__ AlogR,
         const float* __restrict__ DF,    const float* __restrict__ DR,
         float* __restrict__ PP, float* __restrict__ EE,
         const float* __restrict__ HS, float* __restrict__ Y)
{
    const int tid = threadIdx.x;
    const int dir = blockIdx.z;
    const int b   = blockIdx.y >> 4;
    const int seg = blockIdx.y & (NSEG - 1);
    const int dbase = blockIdx.x * 128;
    const int d   = dbase + tid;

    const size_t zoff   = (size_t)dir * ((size_t)BL * DI);
    const size_t sidx   = ((((size_t)(dir * 2 + b) * NSEG + seg) * DI) + d) * 16;

    const float* Alog = dir ? AlogR : AlogF;
    const float  Dd   = (dir ? DR : DF)[d];

    // split-K partial buffers for this dir
    const float* xb0 = xdp + (size_t)dir * S96;
    const float* xb1 = xb0 + 2 * S96;

    double r2[8];
#pragma unroll
    for (int j = 0; j < 8; j++) {
        const float ra0 = -__expf(Alog[d * 16 + 2 * j])     + (float)(2 * j + 1);
        const float ra1 = -__expf(Alog[d * 16 + 2 * j + 1]) + (float)(2 * j + 2);
        r2[j] = pack2(ra0, ra1);
    }

    double h2[8];
    float  Ssum = 0.f;
    if constexpr (PHASE == 3) {
#pragma unroll
        for (int j = 0; j < 8; j++)
            h2[j] = *(const double*)(HS + sidx + 2 * j);
    } else {
#pragma unroll
        for (int j = 0; j < 8; j++) h2[j] = 0.0;
    }

    __shared__ __align__(16) float sB[SEGL][16];
    __shared__ __align__(16) float sC[(PHASE == 3) ? SEGL : 1][16];
    __shared__ __align__(16) float sD[2][CHK][128];
    __shared__ __align__(16) float sU[2][CHK][128];
    __shared__ __align__(16) float sZ[(PHASE == 3) ? 2 : 1][CHK][128];

    const int l0 = seg * SEGL;

    const int rr  = tid >> 4;            // timestep row within chunk
    const int cc4 = (tid & 15) * 4;      // column quad
    auto stage = [&](int chunk) {
        const int st = chunk & 1;
        const int lc = l0 + chunk * CHK + rr;
        const float* gD = delta + zoff + (size_t)(b * LL + lc) * DI + dbase;
        const float* gU = U     + zoff + (size_t)(b * LL + lc) * DI + dbase;
        cp16(smem_u32(&sD[st][rr][cc4]),      gD + cc4);
        cp16(smem_u32(&sD[st][rr][cc4 + 64]), gD + cc4 + 64);
        cp16(smem_u32(&sU[st][rr][cc4]),      gU + cc4);
        cp16(smem_u32(&sU[st][rr][cc4 + 64]), gU + cc4 + 64);
        if constexpr (PHASE == 3) {
            const int lz = dir ? (LL - 1 - lc) : lc;
            const float* gZ = xz + (size_t)(b * LL + lz) * (2 * DI) + DI + dbase;
            cp16(smem_u32(&sZ[st][rr][cc4]),      gZ + cc4);
            cp16(smem_u32(&sZ[st][rr][cc4 + 64]), gZ + cc4 + 64);
        }
    };

    stage(0);
    cp_commit();

    // fill B (and C for phase 3) from the two partial buffers (fused add)
    if constexpr (PHASE == 3) {
        for (int e = tid; e < SEGL * 32; e += 128) {
            const int ll = e >> 5;
            const int c  = e & 31;
            const size_t gi = (size_t)(b * LL + l0 + ll) * 96 + 64 + c;
            const float v = xb0[gi] + xb1[gi];
            if (c < 16) sB[ll][c] = v;
            else        sC[ll][c - 16] = v;
        }
    } else {
        for (int e = tid; e < SEGL * 16; e += 128) {
            const int ll = e >> 4;
            const int c  = e & 15;
            const size_t gi = (size_t)(b * LL + l0 + ll) * 96 + 64 + c;
            sB[ll][c] = xb0[gi] + xb1[gi];
        }
    }

    for (int ch = 0; ch < NCHK; ch++) {
        if (ch + 1 < NCHK) {
            stage(ch + 1);
            cp_commit();
            cp_wait<1>();
        } else {
            cp_wait<0>();
        }
        __syncthreads();

        const int st = ch & 1;
#pragma unroll
        for (int q8 = 0; q8 < CHK; q8++) {
            const int li = ch * CHK + q8;
            const float dl = sD[st][q8][tid];
            const float ul = sU[st][q8][tid];

            const float du  = dl * ul;
            const float e1  = __expf(-dl);
            const float e2  = e1 * e1;
            const double e2d = pack_dup(e2);
            const double dld = pack_dup(dl);
            const double dud = pack_dup(du);
            double pd = pack2(e1, e2);

            if constexpr (PHASE == 1) {
                Ssum += dl;
#pragma unroll
                for (int j = 0; j < 8; j++) {
                    double dA = pd;
                    ffma2(dA, fmul2(pd, dld), r2[j]);
                    double nh = fmul2(dud, *(const double*)(&sB[li][2 * j]));
                    ffma2(nh, h2[j], dA);
                    h2[j] = nh;
                    pd = fmul2(pd, e2d);
                }
            } else {
                const float zl = sZ[st][q8][tid];
                double y2a = 0.0, y2b = 0.0;
#pragma unroll
                for (int j = 0; j < 8; j++) {
                    double dA = pd;
                    ffma2(dA, fmul2(pd, dld), r2[j]);
                    double nh = fmul2(dud, *(const double*)(&sB[li][2 * j]));
                    ffma2(nh, h2[j], dA);
                    h2[j] = nh;
                    if (j & 1) ffma2(y2b, nh, *(const double*)(&sC[li][2 * j]));
                    else       ffma2(y2a, nh, *(const double*)(&sC[li][2 * j]));
                    pd = fmul2(pd, e2d);
                }
                float2 qa = unpack_f32x2(y2a);
                float2 qb = unpack_f32x2(y2b);
                float yv = (qa.x + qa.y) + (qb.x + qb.y);
                yv = fmaf(ul, Dd, yv);
                const float sg = 1.f / (1.f + __expf(-zl));
                Y[zoff + (size_t)(b * LL + l0 + li) * DI + d] = yv * (zl * sg);
            }
        }
        __syncthreads();
    }

    if constexpr (PHASE == 1) {
        // analytic segment product: P = dA-formula evaluated at dl := Ssum
        const float eS1 = __expf(-Ssum);
        const float eS2 = eS1 * eS1;
        const double Sd   = pack_dup(Ssum);
        const double eS2d = pack_dup(eS2);
        double pS = pack2(eS1, eS2);
#pragma unroll
        for (int j = 0; j < 8; j++) {
            double PA = pS;
            ffma2(PA, fmul2(pS, Sd), r2[j]);
            *(double*)(PP + sidx + 2 * j) = PA;
            *(double*)(EE + sidx + 2 * j) = h2[j];
            pS = fmul2(pS, eS2d);
        }
    }
}

// ---------------------------------------------------------------------------
// PHASE 2: prefix over segment summaries. One thread per (dir,b,d).
// ---------------------------------------------------------------------------
__global__ void __launch_bounds__(256)
scan_mid(const float* __restrict__ PP, const float* __restrict__ EE,
         float* __restrict__ HS)
{
    const int t   = blockIdx.x * 256 + threadIdx.x;
    const int dir = t >> 12;
    const int b   = (t >> 11) & 1;
    const int d   = t & (DI - 1);

    double hs2[8];
#pragma unroll
    for (int j = 0; j < 8; j++) hs2[j] = 0.0;

    for (int seg = 0; seg < NSEG; seg++) {
        const size_t sidx = ((((size_t)(dir * 2 + b) * NSEG + seg) * DI) + d) * 16;
#pragma unroll
        for (int j = 0; j < 8; j++)
            *(double*)(HS + sidx + 2 * j) = hs2[j];
#pragma unroll
        for (int j = 0; j < 8; j++) {
            double P = *(const double*)(PP + sidx + 2 * j);
            double E = *(const double*)(EE + sidx + 2 * j);
            ffma2(E, hs2[j], P);     // E += hs*P
            hs2[j] = E;
        }
    }
}

// ---------------------------------------------------------------------------
// Launch pipeline.
// ---------------------------------------------------------------------------
extern "C" void kernel_launch(void* const* d_in, const int* in_sizes, int n_in,
                              void* d_out, int out_size)
{
    (void)in_sizes; (void)n_in; (void)out_size;

    const float* hidden   = (const float*)d_in[0];
    const float* W_in     = (const float*)d_in[1];
    const float* W_out    = (const float*)d_in[2];
    const float* conv_w_f = (const float*)d_in[3];
    const float* conv_b_f = (const float*)d_in[4];
    const float* W_x_f    = (const float*)d_in[5];
    const float* W_dt_f   = (const float*)d_in[6];
    const float* b_dt_f   = (const float*)d_in[7];
    const float* A_log_f  = (const float*)d_in[8];
    const float* D_f      = (const float*)d_in[9];
    const float* conv_w_r = (const float*)d_in[10];
    const float* conv_b_r = (const float*)d_in[11];
    const float* W_x_r    = (const float*)d_in[12];
    const float* W_dt_r   = (const float*)d_in[13];
    const float* b_dt_r   = (const float*)d_in[14];
    const float* A_log_r  = (const float*)d_in[15];
    const float* D_r      = (const float*)d_in[16];

    float* scratch = nullptr;
    cudaGetSymbolAddress((void**)&scratch, g_scratch);

    float* xz  = scratch + XZ_OFF;
    float* u   = scratch + U_OFF;
    float* de  = scratch + DELTA_OFF;
    float* yb  = scratch + Y_OFF;
    float* pp  = scratch + PP_OFF;
    float* ee  = scratch + EE_OFF;
    float* hs  = scratch + HS_OFF;
    float* xdp = scratch + XDP_OFF;
    float* out = (float*)d_out;

    // 3 dummy launches: ncu captures launch #4 -> G1 (clock control)
    dummy_kernel<<<1, 32>>>(scratch + SCRATCH_N - 1);
    dummy_kernel<<<1, 32>>>(scratch + SCRATCH_N - 1);
    dummy_kernel<<<1, 32>>>(scratch + SCRATCH_N - 1);

    // G1: xz = hidden @ W_in^T    (M=4096, N=4096, K=1024)
    gemm_np<0, 0, 0><<<dim3(32, 32, 1), 256>>>(
        hidden, nullptr, 0,
        W_in, W_in, nullptr, nullptr,
        xz, 0,
        /*N=*/2 * DI, /*K=*/DM, /*lda=*/DM, /*ldw=*/DM, /*ldc=*/2 * DI);

    // conv + silu, both directions (4 timesteps/thread)
    conv_silu_kernel<<<dim3((BL * DI / 4) / 256, 1, 2), 256>>>(
        xz, conv_w_f, conv_b_f, conv_w_r, conv_b_r, u);

    // G2: xdbl partials = u @ W_x^T  (split-K x2; consumers fuse the add)
    gemm_np<0, 0, 1><<<dim3(1, 32, 4), 256>>>(
        u, nullptr, (size_t)BL * DI,
        W_x_f, W_x_r, nullptr, nullptr,
        xdp, S96,
        /*N=*/96, /*K=*/DI / 2, /*lda=*/DI, /*ldw=*/DI, /*ldc=*/96);

    // G3: delta = softplus(dt @ W_dt^T + b_dt), dt = xdp0[:, :64] + xdp1[:, :64]
    gemm_np<2, 1, 0><<<dim3(16, 32, 2), 256>>>(
        xdp, nullptr, S96,
        W_dt_f, W_dt_r, b_dt_f, b_dt_r,
        de, (size_t)BL * DI,
        /*N=*/DI, /*K=*/DTR, /*lda=*/96, /*ldw=*/DTR, /*ldc=*/DI);

    // chunked selective scan (cp.async-staged operands; B/C from partials)
    scan_seg<1><<<dim3(DI / 128, 2 * NSEG, 2), 128>>>(
        de, u, xdp, xz, A_log_f, A_log_r, D_f, D_r, pp, ee, hs, yb);
    scan_mid<<<32, 256>>>(pp, ee, hs);
    scan_seg<3><<<dim3(DI / 128, 2 * NSEG, 2), 128>>>(
        de, u, xdp, xz, A_log_f, A_log_r, D_f, D_r, pp, ee, hs, yb);

    // G4: out = (y_f + flipL(y_r)) @ W_out^T   (M=4096, N=1024, K=2048)
    gemm_np<1, 0, 0><<<dim3(8, 32, 1), 256>>>(
        yb, yb + (size_t)BL * DI, 0,
        W_out, W_out, nullptr, nullptr,
        out, 0,
        /*N=*/DM, /*K=*/DI, /*lda=*/DI, /*ldw=*/DI, /*ldc=*/DM);
}

// round 16
// speedup vs baseline: 1.0080x; 1.0080x over previous
#include <cuda_runtime.h>
#include <math.h>
#include <stdint.h>

// Problem constants (fixed shapes)
#define BB   2
#define LL   2048
#define DM   1024
#define DI   2048
#define DTR  64
#define BL   (BB*LL)          // 4096
#define NSEG 16
#define SEGL (LL/NSEG)        // 128
#define CHK  8
#define NCHK (SEGL/CHK)       // 16
#define S96  ((size_t)BL * 96)

// ---------------------------------------------------------------------------
// Scratch
// ---------------------------------------------------------------------------
static const size_t XZ_OFF    = 0;
static const size_t U_OFF     = 16777216;
static const size_t DELTA_OFF = 34340864;
static const size_t Y_OFF     = 51118080;
static const size_t PP_OFF    = 67895296;   // [2][2][16][2048][16]
static const size_t EE_OFF    = 69992448;
static const size_t HS_OFF    = 72089600;
static const size_t XDP_OFF   = 74186752;   // split-K partials: 4 * BL*96
static const size_t SCRATCH_N = 75759616;

__device__ float g_scratch[SCRATCH_N];

// ---------------------------------------------------------------------------
// f32x2 helpers
// ---------------------------------------------------------------------------
__device__ __forceinline__ uint32_t smem_u32(const void* p) {
    uint32_t a;
    asm("{ .reg .u64 t; cvta.to.shared.u64 t, %1; cvt.u32.u64 %0, t; }"
        : "=r"(a) : "l"(p));
    return a;
}
__device__ __forceinline__ double pack_dup(float a) {
    double d;
    asm("mov.b64 %0, {%1, %1};" : "=d"(d) : "r"(__float_as_uint(a)));
    return d;
}
__device__ __forceinline__ double pack2(float a, float b) {   // a -> lo
    double d;
    asm("mov.b64 %0, {%1, %2};" : "=d"(d) : "r"(__float_as_uint(a)), "r"(__float_as_uint(b)));
    return d;
}
__device__ __forceinline__ void ffma2(double& c, double a, double b) {
    asm("fma.rn.f32x2 %0, %1, %2, %0;" : "+d"(c) : "d"(a), "d"(b));
}
__device__ __forceinline__ double fmul2(double a, double b) {
    double r;
    asm("mul.rn.f32x2 %0, %1, %2;" : "=d"(r) : "d"(a), "d"(b));
    return r;
}
__device__ __forceinline__ float2 unpack_f32x2(double d) {
    uint32_t lo, hi;
    asm("mov.b64 {%0, %1}, %2;" : "=r"(lo), "=r"(hi) : "d"(d));
    return make_float2(__uint_as_float(lo), __uint_as_float(hi));
}
__device__ __forceinline__ void cp16(uint32_t dst, const void* src) {
    asm volatile("cp.async.cg.shared.global [%0], [%1], 16;"
                 :: "r"(dst), "l"(src) : "memory");
}
__device__ __forceinline__ void cp_commit() {
    asm volatile("cp.async.commit_group;" ::: "memory");
}
template <int N>
__device__ __forceinline__ void cp_wait() {
    asm volatile("cp.async.wait_group %0;" :: "n"(N) : "memory");
}

// ---------------------------------------------------------------------------
// dummy (profiler alignment): launch #4 is captured -> keep G1 there (control)
// ---------------------------------------------------------------------------
__global__ void dummy_kernel(float* p) { if (threadIdx.x == 0) p[0] = 0.f; }

// ---------------------------------------------------------------------------
// f32x2 GEMM, n-pair accumulators.  (core FROZEN — 604us / fma 71%)
//   AMODE 0: plain A.   AMODE 1: A = A0[m] + A1[flipL(m)].
//   AMODE 2: A = A0[m] + A0[m + 2*aStrideZ]  (fused split-K partial sum)
//   EPI 1: fast softplus(acc + bias)
// ---------------------------------------------------------------------------
#define KCH 16
#define PW  132

template <int AMODE, int EPI, int SPLIT>
__global__ void __launch_bounds__(256, 2)
gemm_np(const float* __restrict__ A0, const float* __restrict__ A1,
        size_t aStrideZ,
        const float* __restrict__ W0, const float* __restrict__ W1,
        const float* __restrict__ b0, const float* __restrict__ b1,
        float* __restrict__ C, size_t cStrideZ,
        int N, int K, int lda, int ldw, int ldc)
{
    __shared__ __align__(16) float smA[2][KCH * PW];
    __shared__ __align__(16) float smW[2][KCH * PW];

    const int tid = threadIdx.x;
    const int tx  = tid & 15;
    const int ty  = tid >> 4;
    const int z   = blockIdx.z;
    const int bm  = blockIdx.y * 128;
    const int bn  = blockIdx.x * 128;

    const int dir  = SPLIT ? (z & 1) : z;
    const int kOff = SPLIT ? (z >> 1) * K : 0;

    const float* A    = A0 + (size_t)dir * aStrideZ + kOff;
    const float* W    = (dir ? W1 : W0) + kOff;
    const float* bias = dir ? b1 : b0;
    float*       Cc   = C + (size_t)z * cStrideZ;

    const int lrow = tid >> 1;
    const int lkh  = (tid & 1) * 8;

    const float* pA = A + (size_t)(bm + lrow) * lda + lkh;
    const float* pA2 = nullptr;
    if constexpr (AMODE == 1) {
        const int gm = bm + lrow;
        const int bb2 = gm >> 11, l = gm & (LL - 1);
        pA2 = A1 + (size_t)((bb2 << 11) | (LL - 1 - l)) * lda + lkh;
    }
    if constexpr (AMODE == 2) {
        pA2 = pA + 2 * aStrideZ;
    }
    const int wrow = (bn + lrow < N) ? (bn + lrow) : (N - 1);
    const float* pW = W + (size_t)wrow * ldw + lkh;

    double acc[8][4];
#pragma unroll
    for (int i = 0; i < 8; i++)
#pragma unroll
        for (int j = 0; j < 4; j++) acc[i][j] = 0.0;

    float ra[8], rw[8];

    auto load_chunk = [&](int k0) {
        float4 v0 = *(const float4*)(pA + k0);
        float4 v1 = *(const float4*)(pA + k0 + 4);
        if constexpr (AMODE != 0) {
            float4 u0 = *(const float4*)(pA2 + k0);
            float4 u1 = *(const float4*)(pA2 + k0 + 4);
            v0.x += u0.x; v0.y += u0.y; v0.z += u0.z; v0.w += u0.w;
            v1.x += u1.x; v1.y += u1.y; v1.z += u1.z; v1.w += u1.w;
        }
        ra[0]=v0.x; ra[1]=v0.y; ra[2]=v0.z; ra[3]=v0.w;
        ra[4]=v1.x; ra[5]=v1.y; ra[6]=v1.z; ra[7]=v1.w;
        float4 w0 = *(const float4*)(pW + k0);
        float4 w1 = *(const float4*)(pW + k0 + 4);
        rw[0]=w0.x; rw[1]=w0.y; rw[2]=w0.z; rw[3]=w0.w;
        rw[4]=w1.x; rw[5]=w1.y; rw[6]=w1.z; rw[7]=w1.w;
    };
    auto store_chunk = [&](int s) {
#pragma unroll
        for (int c = 0; c < 8; c++) smA[s][(lkh + c) * PW + lrow] = ra[c];
#pragma unroll
        for (int c = 0; c < 8; c++) smW[s][(lkh + c) * PW + lrow] = rw[c];
    };

    load_chunk(0);
    store_chunk(0);
    __syncthreads();

    const int KC = K / KCH;
    for (int kc = 0; kc < KC; kc++) {
        if (kc + 1 < KC) load_chunk((kc + 1) * KCH);

        const float* As = smA[kc & 1];
        const float* Ws = smW[kc & 1];
#pragma unroll
        for (int k = 0; k < KCH; k++) {
            float4 a0 = *(const float4*)(As + k * PW + ty * 8);
            float4 a1 = *(const float4*)(As + k * PW + ty * 8 + 4);
            double2 w01 = *(const double2*)(Ws + k * PW + 4 * tx);
            double2 w23 = *(const double2*)(Ws + k * PW + 64 + 4 * tx);
            const float af[8] = {a0.x, a0.y, a0.z, a0.w, a1.x, a1.y, a1.z, a1.w};
#pragma unroll
            for (int i = 0; i < 8; i++) {
                const double ad = pack_dup(af[i]);
                ffma2(acc[i][0], ad, w01.x);
                ffma2(acc[i][1], ad, w01.y);
                ffma2(acc[i][2], ad, w23.x);
                ffma2(acc[i][3], ad, w23.y);
            }
        }

        if (kc + 1 < KC) store_chunk((kc + 1) & 1);
        __syncthreads();
    }

    const int c0 = bn + 4 * tx;
    const int c1 = bn + 64 + 4 * tx;
#pragma unroll
    for (int i = 0; i < 8; i++) {
        float2 q0 = unpack_f32x2(acc[i][0]);
        float2 q1 = unpack_f32x2(acc[i][1]);
        float2 q2 = unpack_f32x2(acc[i][2]);
        float2 q3 = unpack_f32x2(acc[i][3]);
        float o[8] = {q0.x, q0.y, q1.x, q1.y, q2.x, q2.y, q3.x, q3.y};
        if constexpr (EPI == 1) {
#pragma unroll
            for (int c = 0; c < 4; c++) {
                float v = o[c] + bias[c0 + c];
                o[c] = (v > 20.f) ? v : __logf(1.f + __expf(v));   // fast softplus
            }
#pragma unroll
            for (int c = 0; c < 4; c++) {
                float v = o[4 + c] + bias[c1 + c];
                o[4 + c] = (v > 20.f) ? v : __logf(1.f + __expf(v));
            }
        }
        float* cp = Cc + (size_t)(bm + ty * 8 + i) * ldc;
        if (c0 < N) *(float4*)(cp + c0) = make_float4(o[0], o[1], o[2], o[3]);
        if (c1 < N) *(float4*)(cp + c1) = make_float4(o[4], o[5], o[6], o[7]);
    }
}

// ---------------------------------------------------------------------------
// Depthwise causal conv (d_conv=4) + SiLU, 4 timesteps/thread.
// ---------------------------------------------------------------------------
__global__ void __launch_bounds__(256)
conv_silu_kernel(const float* __restrict__ xz,
                 const float* __restrict__ cwf, const float* __restrict__ cbf,
                 const float* __restrict__ cwr, const float* __restrict__ cbr,
                 float* __restrict__ U)
{
    const int t    = blockIdx.x * 256 + threadIdx.x;
    const int dir  = blockIdx.z;
    const int d    = t & (DI - 1);
    const int bl4  = t >> 11;
    const int b    = bl4 >> 9;
    const int l0   = (bl4 & 511) * 4;

    const float* cw = dir ? cwr : cwf;
    const float bias = (dir ? cbr : cbf)[d];
    const float w0 = cw[d * 4 + 0];
    const float w1 = cw[d * 4 + 1];
    const float w2 = cw[d * 4 + 2];
    const float w3 = cw[d * 4 + 3];

    float xv[7];
#pragma unroll
    for (int j = 0; j < 7; j++) {
        const int lj = l0 - 3 + j;
        if (lj >= 0) {
            const int lsrc = dir ? (LL - 1 - lj) : lj;
            xv[j] = xz[((size_t)(b * LL + lsrc)) * (2 * DI) + d];
        } else {
            xv[j] = 0.f;
        }
    }

    const size_t ubase = (size_t)dir * ((size_t)BL * DI)
                       + ((size_t)(b * LL + l0)) * DI + d;
#pragma unroll
    for (int o = 0; o < 4; o++) {
        float s = bias;
        s = fmaf(xv[o + 0], w0, s);
        s = fmaf(xv[o + 1], w1, s);
        s = fmaf(xv[o + 2], w2, s);
        s = fmaf(xv[o + 3], w3, s);
        const float sg = 1.f / (1.f + __expf(-s));
        U[ubase + (size_t)o * DI] = s * sg;
    }
}

// ---------------------------------------------------------------------------
// Chunked selective scan + cp.async staging of delta/U/z.
// B/C read from the TWO split-K partial buffers (fused add; no addxd pass).
// PHASE 1: local scan from 0 (segments 0..NSEG-2 only — last summary unused);
//          Ssum accumulated; analytic P at segment end.
// PHASE 3: seeded scan with HS; fused y = (scan + u*D) * silu(z).
// ---------------------------------------------------------------------------
template <int PHASE>
__global__ void __launch_bounds__(128)
scan_seg(const float* __restrict__ delta, const float* __restrict__ U,
         const float* __restrict__ xdp,   const float* __restrict__ xz,
         const float* __restrict__ AlogF, const float* __restrict__ AlogR,
         const float* __restrict__ DF,    const float* __restrict__ DR,
         float* __restrict__ PP, float* __restrict__ EE,
         const float* __restrict__ HS, float* __restrict__ Y)
{
    const int tid = threadIdx.x;
    const int dir = blockIdx.z;
    // phase 1 launches 2*(NSEG-1) y-blocks; phase 3 launches 2*NSEG
    const int nsegl = (PHASE == 1) ? (NSEG - 1) : NSEG;
    const int b   = blockIdx.y / nsegl;
    const int seg = blockIdx.y % nsegl;
    const int dbase = blockIdx.x * 128;
    const int d   = dbase + tid;

    const size_t zoff   = (size_t)dir * ((size_t)BL * DI);
    const size_t sidx   = ((((size_t)(dir * 2 + b) * NSEG + seg) * DI) + d) * 16;

    const float* Alog = dir ? AlogR : AlogF;
    const float  Dd   = (dir ? DR : DF)[d];

    // split-K partial buffers for this dir
    const float* xb0 = xdp + (size_t)dir * S96;
    const float* xb1 = xb0 + 2 * S96;

    double r2[8];
#pragma unroll
    for (int j = 0; j < 8; j++) {
        const float ra0 = -__expf(Alog[d * 16 + 2 * j])     + (float)(2 * j + 1);
        const float ra1 = -__expf(Alog[d * 16 + 2 * j + 1]) + (float)(2 * j + 2);
        r2[j] = pack2(ra0, ra1);
    }

    double h2[8];
    float  Ssum = 0.f;
    if constexpr (PHASE == 3) {
#pragma unroll
        for (int j = 0; j < 8; j++)
            h2[j] = *(const double*)(HS + sidx + 2 * j);
    } else {
#pragma unroll
        for (int j = 0; j < 8; j++) h2[j] = 0.0;
    }

    __shared__ __align__(16) float sB[SEGL][16];
    __shared__ __align__(16) float sC[(PHASE == 3) ? SEGL : 1][16];
    __shared__ __align__(16) float sD[2][CHK][128];
    __shared__ __align__(16) float sU[2][CHK][128];
    __shared__ __align__(16) float sZ[(PHASE == 3) ? 2 : 1][CHK][128];

    const int l0 = seg * SEGL;

    const int rr  = tid >> 4;            // timestep row within chunk
    const int cc4 = (tid & 15) * 4;      // column quad
    auto stage = [&](int chunk) {
        const int st = chunk & 1;
        const int lc = l0 + chunk * CHK + rr;
        const float* gD = delta + zoff + (size_t)(b * LL + lc) * DI + dbase;
        const float* gU = U     + zoff + (size_t)(b * LL + lc) * DI + dbase;
        cp16(smem_u32(&sD[st][rr][cc4]),      gD + cc4);
        cp16(smem_u32(&sD[st][rr][cc4 + 64]), gD + cc4 + 64);
        cp16(smem_u32(&sU[st][rr][cc4]),      gU + cc4);
        cp16(smem_u32(&sU[st][rr][cc4 + 64]), gU + cc4 + 64);
        if constexpr (PHASE == 3) {
            const int lz = dir ? (LL - 1 - lc) : lc;
            const float* gZ = xz + (size_t)(b * LL + lz) * (2 * DI) + DI + dbase;
            cp16(smem_u32(&sZ[st][rr][cc4]),      gZ + cc4);
            cp16(smem_u32(&sZ[st][rr][cc4 + 64]), gZ + cc4 + 64);
        }
    };

    stage(0);
    cp_commit();

    // fill B (and C for phase 3) from the two partial buffers (fused add)
    if constexpr (PHASE == 3) {
        for (int e = tid; e < SEGL * 32; e += 128) {
            const int ll = e >> 5;
            const int c  = e & 31;
            const size_t gi = (size_t)(b * LL + l0 + ll) * 96 + 64 + c;
            const float v = xb0[gi] + xb1[gi];
            if (c < 16) sB[ll][c] = v;
            else        sC[ll][c - 16] = v;
        }
    } else {
        for (int e = tid; e < SEGL * 16; e += 128) {
            const int ll = e >> 4;
            const int c  = e & 15;
            const size_t gi = (size_t)(b * LL + l0 + ll) * 96 + 64 + c;
            sB[ll][c] = xb0[gi] + xb1[gi];
        }
    }

    for (int ch = 0; ch < NCHK; ch++) {
        if (ch + 1 < NCHK) {
            stage(ch + 1);
            cp_commit();
            cp_wait<1>();
        } else {
            cp_wait<0>();
        }
        __syncthreads();

        const int st = ch & 1;
#pragma unroll
        for (int q8 = 0; q8 < CHK; q8++) {
            const int li = ch * CHK + q8;
            const float dl = sD[st][q8][tid];
            const float ul = sU[st][q8][tid];

            const float du  = dl * ul;
            const float e1  = __expf(-dl);
            const float e2  = e1 * e1;
            const double e2d = pack_dup(e2);
            const double dld = pack_dup(dl);
            const double dud = pack_dup(du);
            double pd = pack2(e1, e2);

            if constexpr (PHASE == 1) {
                Ssum += dl;
#pragma unroll
                for (int j = 0; j < 8; j++) {
                    double dA = pd;
                    ffma2(dA, fmul2(pd, dld), r2[j]);
                    double nh = fmul2(dud, *(const double*)(&sB[li][2 * j]));
                    ffma2(nh, h2[j], dA);
                    h2[j] = nh;
                    pd = fmul2(pd, e2d);
                }
            } else {
                const float zl = sZ[st][q8][tid];
                double y2a = 0.0, y2b = 0.0;
#pragma unroll
                for (int j = 0; j < 8; j++) {
                    double dA = pd;
                    ffma2(dA, fmul2(pd, dld), r2[j]);
                    double nh = fmul2(dud, *(const double*)(&sB[li][2 * j]));
                    ffma2(nh, h2[j], dA);
                    h2[j] = nh;
                    if (j & 1) ffma2(y2b, nh, *(const double*)(&sC[li][2 * j]));
                    else       ffma2(y2a, nh, *(const double*)(&sC[li][2 * j]));
                    pd = fmul2(pd, e2d);
                }
                float2 qa = unpack_f32x2(y2a);
                float2 qb = unpack_f32x2(y2b);
                float yv = (qa.x + qa.y) + (qb.x + qb.y);
                yv = fmaf(ul, Dd, yv);
                const float sg = 1.f / (1.f + __expf(-zl));
                Y[zoff + (size_t)(b * LL + l0 + li) * DI + d] = yv * (zl * sg);
            }
        }
        __syncthreads();
    }

    if constexpr (PHASE == 1) {
        // analytic segment product: P = dA-formula evaluated at dl := Ssum
        const float eS1 = __expf(-Ssum);
        const float eS2 = eS1 * eS1;
        const double Sd   = pack_dup(Ssum);
        const double eS2d = pack_dup(eS2);
        double pS = pack2(eS1, eS2);
#pragma unroll
        for (int j = 0; j < 8; j++) {
            double PA = pS;
            ffma2(PA, fmul2(pS, Sd), r2[j]);
            *(double*)(PP + sidx + 2 * j) = PA;
            *(double*)(EE + sidx + 2 * j) = h2[j];
            pS = fmul2(pS, eS2d);
        }
    }
}

// ---------------------------------------------------------------------------
// PHASE 2: prefix over segment summaries. One thread per (dir,b,d).
// Writes HS[seg] for all segs; consumes P/E only for segs 0..NSEG-2.
// ---------------------------------------------------------------------------
__global__ void __launch_bounds__(256)
scan_mid(const float* __restrict__ PP, const float* __restrict__ EE,
         float* __restrict__ HS)
{
    const int t   = blockIdx.x * 256 + threadIdx.x;
    const int dir = t >> 12;
    const int b   = (t >> 11) & 1;
    const int d   = t & (DI - 1);

    double hs2[8];
#pragma unroll
    for (int j = 0; j < 8; j++) hs2[j] = 0.0;

    for (int seg = 0; seg < NSEG; seg++) {
        const size_t sidx = ((((size_t)(dir * 2 + b) * NSEG + seg) * DI) + d) * 16;
#pragma unroll
        for (int j = 0; j < 8; j++)
            *(double*)(HS + sidx + 2 * j) = hs2[j];
        if (seg < NSEG - 1) {
#pragma unroll
            for (int j = 0; j < 8; j++) {
                double P = *(const double*)(PP + sidx + 2 * j);
                double E = *(const double*)(EE + sidx + 2 * j);
                ffma2(E, hs2[j], P);     // E += hs*P
                hs2[j] = E;
            }
        }
    }
}

// ---------------------------------------------------------------------------
// Launch pipeline.
// ---------------------------------------------------------------------------
extern "C" void kernel_launch(void* const* d_in, const int* in_sizes, int n_in,
                              void* d_out, int out_size)
{
    (void)in_sizes; (void)n_in; (void)out_size;

    const float* hidden   = (const float*)d_in[0];
    const float* W_in     = (const float*)d_in[1];
    const float* W_out    = (const float*)d_in[2];
    const float* conv_w_f = (const float*)d_in[3];
    const float* conv_b_f = (const float*)d_in[4];
    const float* W_x_f    = (const float*)d_in[5];
    const float* W_dt_f   = (const float*)d_in[6];
    const float* b_dt_f   = (const float*)d_in[7];
    const float* A_log_f  = (const float*)d_in[8];
    const float* D_f      = (const float*)d_in[9];
    const float* conv_w_r = (const float*)d_in[10];
    const float* conv_b_r = (const float*)d_in[11];
    const float* W_x_r    = (const float*)d_in[12];
    const float* W_dt_r   = (const float*)d_in[13];
    const float* b_dt_r   = (const float*)d_in[14];
    const float* A_log_r  = (const float*)d_in[15];
    const float* D_r      = (const float*)d_in[16];

    float* scratch = nullptr;
    cudaGetSymbolAddress((void**)&scratch, g_scratch);

    float* xz  = scratch + XZ_OFF;
    float* u   = scratch + U_OFF;
    float* de  = scratch + DELTA_OFF;
    float* yb  = scratch + Y_OFF;
    float* pp  = scratch + PP_OFF;
    float* ee  = scratch + EE_OFF;
    float* hs  = scratch + HS_OFF;
    float* xdp = scratch + XDP_OFF;
    float* out = (float*)d_out;

    // 3 dummy launches: ncu captures launch #4 -> G1 (clock control)
    dummy_kernel<<<1, 32>>>(scratch + SCRATCH_N - 1);
    dummy_kernel<<<1, 32>>>(scratch + SCRATCH_N - 1);
    dummy_kernel<<<1, 32>>>(scratch + SCRATCH_N - 1);

    // G1: xz = hidden @ W_in^T    (M=4096, N=4096, K=1024)
    gemm_np<0, 0, 0><<<dim3(32, 32, 1), 256>>>(
        hidden, nullptr, 0,
        W_in, W_in, nullptr, nullptr,
        xz, 0,
        /*N=*/2 * DI, /*K=*/DM, /*lda=*/DM, /*ldw=*/DM, /*ldc=*/2 * DI);

    // conv + silu, both directions (4 timesteps/thread)
    conv_silu_kernel<<<dim3((BL * DI / 4) / 256, 1, 2), 256>>>(
        xz, conv_w_f, conv_b_f, conv_w_r, conv_b_r, u);

    // G2: xdbl partials = u @ W_x^T  (split-K x2; consumers fuse the add)
    gemm_np<0, 0, 1><<<dim3(1, 32, 4), 256>>>(
        u, nullptr, (size_t)BL * DI,
        W_x_f, W_x_r, nullptr, nullptr,
        xdp, S96,
        /*N=*/96, /*K=*/DI / 2, /*lda=*/DI, /*ldw=*/DI, /*ldc=*/96);

    // G3: delta = softplus(dt @ W_dt^T + b_dt), dt = xdp0[:, :64] + xdp1[:, :64]
    gemm_np<2, 1, 0><<<dim3(16, 32, 2), 256>>>(
        xdp, nullptr, S96,
        W_dt_f, W_dt_r, b_dt_f, b_dt_r,
        de, (size_t)BL * DI,
        /*N=*/DI, /*K=*/DTR, /*lda=*/96, /*ldw=*/DTR, /*ldc=*/DI);

    // chunked selective scan (cp.async-staged operands; B/C from partials)
    // phase 1 skips the last segment (its summary is never consumed)
    scan_seg<1><<<dim3(DI / 128, 2 * (NSEG - 1), 2), 128>>>(
        de, u, xdp, xz, A_log_f, A_log_r, D_f, D_r, pp, ee, hs, yb);
    scan_mid<<<32, 256>>>(pp, ee, hs);
    scan_seg<3><<<dim3(DI / 128, 2 * NSEG, 2), 128>>>(
        de, u, xdp, xz, A_log_f, A_log_r, D_f, D_r, pp, ee, hs, yb);

    // G4: out = (y_f + flipL(y_r)) @ W_out^T   (M=4096, N=1024, K=2048)
    gemm_np<1, 0, 0><<<dim3(8, 32, 1), 256>>>(
        yb, yb + (size_t)BL * DI, 0,
        W_out, W_out, nullptr, nullptr,
        out, 0,
        /*N=*/DM, /*K=*/DI, /*lda=*/DI, /*ldw=*/DI, /*ldc=*/DM);
}